// round 14
// baseline (speedup 1.0000x reference)
#include <cuda_runtime.h>
#include <cuda_bf16.h>
#include <math.h>
#include <stdint.h>

#define NI 2304          // B*H*W
#define S_LEN 77
#define NQ 80
#define HID 128
#define EPS 1e-6f

typedef unsigned long long u64;

// ---------------- scratch (device globals; allocation-free) ----------------
__device__ float g_K[NI * S_LEN * HID];
__device__ float g_V[NI * S_LEN * HID];
__device__ float g_Q[NI * NQ * HID];

// Pre-split padded weight images: per 32-K chunk, 32 rows x 136 (128 + 8 pad) bf16.
#define B_STR 136
#define CHUNK_ELEMS (32 * B_STR)          // 4352 elems = 8704 bytes
__device__ __align__(16) __nv_bfloat16 g_Bk_hi[8 * CHUNK_ELEMS], g_Bk_lo[8 * CHUNK_ELEMS];
__device__ __align__(16) __nv_bfloat16 g_Bv_hi[4 * CHUNK_ELEMS], g_Bv_lo[4 * CHUNK_ELEMS];
__device__ __align__(16) __nv_bfloat16 g_Bq_hi[8 * CHUNK_ELEMS], g_Bq_lo[8 * CHUNK_ELEMS];

__device__ __forceinline__ float fmap(float t) {
    return t > 0.0f ? t + 1.0f : __expf(t);   // elu+1
}

__device__ __forceinline__ uint32_t s2u(const void* p) {
    uint32_t a;
    asm("{ .reg .u64 t; cvta.to.shared.u64 t, %1; cvt.u32.u64 %0, t; }" : "=r"(a) : "l"(p));
    return a;
}

#define LDSM_X4(r0, r1, r2, r3, addr) \
    asm volatile("ldmatrix.sync.aligned.m8n8.x4.shared.b16 {%0,%1,%2,%3}, [%4];" \
        : "=r"(r0), "=r"(r1), "=r"(r2), "=r"(r3) : "r"(addr))

#define LDSM_X4T(r0, r1, r2, r3, addr) \
    asm volatile("ldmatrix.sync.aligned.m8n8.x4.trans.shared.b16 {%0,%1,%2,%3}, [%4];" \
        : "=r"(r0), "=r"(r1), "=r"(r2), "=r"(r3) : "r"(addr))

#define MMA_BF16(d, a, b0, b1) \
    asm volatile("mma.sync.aligned.m16n8k16.row.col.f32.bf16.bf16.f32 " \
        "{%0,%1,%2,%3}, {%4,%5,%6,%7}, {%8,%9}, {%0,%1,%2,%3};" \
        : "+f"((d)[0]), "+f"((d)[1]), "+f"((d)[2]), "+f"((d)[3]) \
        : "r"((a)[0]), "r"((a)[1]), "r"((a)[2]), "r"((a)[3]), "r"(b0), "r"(b1))

#define CP_ASYNC16(dst, src) \
    asm volatile("cp.async.cg.shared.global [%0], [%1], 16;" :: "r"(dst), "l"(src) : "memory")
#define CP_COMMIT() asm volatile("cp.async.commit_group;" ::: "memory")
#define CP_WAIT0()  asm volatile("cp.async.wait_group 0;"  ::: "memory")
#define CP_WAIT1()  asm volatile("cp.async.wait_group 1;"  ::: "memory")

#define BAR_SYNC(id, cnt) \
    asm volatile("bar.sync %0, %1;" :: "r"(id), "r"(cnt) : "memory")

// ---------------------------------------------------------------------------
// Weight prep: truncation-split W(KDEPTH x 128) -> padded bf16 hi/lo chunk images.
// ---------------------------------------------------------------------------
template<int MODE>
__global__ void prep_w(const float* __restrict__ W)
{
    constexpr int NCHUNK = (MODE == 1) ? 4 : 8;
    __nv_bfloat16* hi = (MODE == 0) ? g_Bk_hi : (MODE == 1 ? g_Bv_hi : g_Bq_hi);
    __nv_bfloat16* lo = (MODE == 0) ? g_Bk_lo : (MODE == 1 ? g_Bv_lo : g_Bq_lo);

    int idx = blockIdx.x * 256 + threadIdx.x;
    if (idx >= NCHUNK * 4096) return;
    int c = idx >> 12;
    int r = (idx >> 7) & 31;
    int n = idx & 127;
    float v = W[(c * 32 + r) * 128 + n];
    uint32_t vb = __float_as_uint(v);
    float hf = __uint_as_float(vb & 0xFFFF0000u);
    hi[(c * 32 + r) * B_STR + n] = __ushort_as_bfloat16((unsigned short)(vb >> 16));
    lo[(c * 32 + r) * B_STR + n] = __float2bfloat16(v - hf);
}

// ---------------------------------------------------------------------------
// Multistage HMMA bf16 split GEMM — ONE __syncthreads per K-chunk.
// A: 2-stage smem (reg prefetch -> alternate stage, no pre-store barrier).
// B: 3-stage cp.async ring (issue c+2 without waiting on c's readers).
// Dynamic smem layout (93696 B):
//   [0,512)             bias
//   A stage st (st=0,1):  hi at 512+st*20480,  lo at +10240
//   B buf b (b=0,1,2):    hi at 41472+b*17408, lo at +8704
// ---------------------------------------------------------------------------
#define A_STR 40
#define OFF_AH(st)  (512 + (st) * 20480)
#define OFF_AL(st)  (512 + (st) * 20480 + 10240)
#define OFF_BH(b)   (41472 + (b) * 17408)
#define OFF_BL(b)   (41472 + (b) * 17408 + 8704)
#define SMEM_SZ     93696

template<int KDEPTH, int MODE>
__global__ __launch_bounds__(256, 2)
void gemm_mma(const float* __restrict__ A1, const float* __restrict__ A2,
              const float* __restrict__ bias)
{
    extern __shared__ __align__(16) char smem[];
    constexpr int NC = KDEPTH / 32;

    float* outp = (MODE == 0) ? g_K : (MODE == 1 ? g_V : g_Q);
    const __nv_bfloat16* img_hi = (MODE == 0) ? g_Bk_hi : (MODE == 1 ? g_Bv_hi : g_Bq_hi);
    const __nv_bfloat16* img_lo = (MODE == 0) ? g_Bk_lo : (MODE == 1 ? g_Bv_lo : g_Bq_lo);

    const int t    = threadIdx.x;
    const int lane = t & 31;
    const int wid  = t >> 5;
    const int wm   = wid & 3;
    const int wn   = wid >> 2;
    const int m0   = blockIdx.x * 128;

    if (t < 128) ((float*)smem)[t] = bias[t];

    const uint32_t sb = s2u(smem);

    // Hoisted A row pointers (4 rows per thread: r = (t>>3) + it*32)
    const int k4     = (t & 7) << 2;
    const int r_base = t >> 3;
    const float* rowp[4];
    ptrdiff_t gdelta = 0;
    #pragma unroll
    for (int it = 0; it < 4; it++) {
        int r = r_base + it * 32;
        int m = m0 + r;
        if (MODE == 2) {
            int ni = m / NQ; int l = m - ni * NQ;
            int b = ni / 576; int rem = ni - b * 576;
            rowp[it] = A1 + (size_t)((b * NQ + l) * 576 + rem) * 256;
        } else {
            rowp[it] = A1 + (size_t)m * 128;
        }
    }
    if (MODE == 0) gdelta = A2 - A1;

    float acc[2][8][4];
    #pragma unroll
    for (int mt = 0; mt < 2; mt++)
        #pragma unroll
        for (int nt = 0; nt < 8; nt++)
            #pragma unroll
            for (int j = 0; j < 4; j++) acc[mt][nt][j] = 0.0f;

    const int l15 = lane & 15;
    const int l16 = (lane >> 4) * 8;

    float4 apf[4];   // A prefetch registers

    auto lda = [&](int c) {
        const int kg = c * 32 + k4;
        #pragma unroll
        for (int it = 0; it < 4; it++) {
            const float* src;
            if (MODE == 0)
                src = (kg >= 128) ? (rowp[it] + gdelta + (kg - 128)) : (rowp[it] + kg);
            else
                src = rowp[it] + kg;
            apf[it] = *(const float4*)src;
        }
    };
    auto sta = [&](int st) {
        #pragma unroll
        for (int it = 0; it < 4; it++) {
            float4 v = apf[it];
            uint32_t bx = __float_as_uint(v.x), by = __float_as_uint(v.y);
            uint32_t bz = __float_as_uint(v.z), bw = __float_as_uint(v.w);
            uint32_t hi01, hi23, lo01, lo23;
            asm("prmt.b32 %0, %1, %2, 0x7632;" : "=r"(hi01) : "r"(bx), "r"(by));
            asm("prmt.b32 %0, %1, %2, 0x7632;" : "=r"(hi23) : "r"(bz), "r"(bw));
            float lx = v.x - __uint_as_float(bx & 0xFFFF0000u);
            float ly = v.y - __uint_as_float(by & 0xFFFF0000u);
            float lz = v.z - __uint_as_float(bz & 0xFFFF0000u);
            float lw = v.w - __uint_as_float(bw & 0xFFFF0000u);
            asm("cvt.rn.bf16x2.f32 %0, %1, %2;" : "=r"(lo01) : "f"(ly), "f"(lx));
            asm("cvt.rn.bf16x2.f32 %0, %1, %2;" : "=r"(lo23) : "f"(lw), "f"(lz));
            int off = (r_base + it * 32) * (A_STR * 2) + k4 * 2;
            *(u64*)(smem + OFF_AH(st) + off) = (u64)hi01 | ((u64)hi23 << 32);
            *(u64*)(smem + OFF_AL(st) + off) = (u64)lo01 | ((u64)lo23 << 32);
        }
    };
    auto ldb = [&](int c, int buf) {
        const char* ih = (const char*)img_hi + (size_t)c * 8704;
        const char* il = (const char*)img_lo + (size_t)c * 8704;
        const uint32_t bh = sb + OFF_BH(buf), bl = sb + OFF_BL(buf);
        for (int i = t; i < 1088; i += 256) {
            bool isHi = i < 544;
            int o = (isHi ? i : i - 544) * 16;
            CP_ASYNC16((isHi ? bh : bl) + o, (isHi ? ih : il) + o);
        }
        CP_COMMIT();
    };
    auto compute = [&](int c) {
        const uint32_t sBh = sb + OFF_BH(c % 3), sBl = sb + OFF_BL(c % 3);
        const uint32_t sAh = sb + OFF_AH(c & 1), sAl = sb + OFF_AL(c & 1);
        #pragma unroll
        for (int ks = 0; ks < 2; ks++) {
            uint32_t bh[4][4], bl[4][4];
            #pragma unroll
            for (int ng = 0; ng < 4; ng++) {
                uint32_t ba = (uint32_t)((ks * 16 + l15) * (B_STR * 2)
                             + (wn * 64 + ng * 16 + l16) * 2);
                LDSM_X4T(bh[ng][0], bh[ng][1], bh[ng][2], bh[ng][3], sBh + ba);
                LDSM_X4T(bl[ng][0], bl[ng][1], bl[ng][2], bl[ng][3], sBl + ba);
            }
            #pragma unroll
            for (int mt = 0; mt < 2; mt++) {
                uint32_t aa = (uint32_t)((wm * 32 + mt * 16 + l15) * (A_STR * 2)
                             + (ks * 16 + l16) * 2);
                uint32_t ah[4], al[4];
                LDSM_X4(ah[0], ah[1], ah[2], ah[3], sAh + aa);
                LDSM_X4(al[0], al[1], al[2], al[3], sAl + aa);
                #pragma unroll
                for (int nt = 0; nt < 8; nt++) {
                    const int ng = nt >> 1, hf = (nt & 1) * 2;
                    MMA_BF16(acc[mt][nt], ah, bh[ng][hf], bh[ng][hf + 1]);
                    MMA_BF16(acc[mt][nt], ah, bl[ng][hf], bl[ng][hf + 1]);
                    MMA_BF16(acc[mt][nt], al, bh[ng][hf], bh[ng][hf + 1]);
                }
            }
        }
    };

    // ---- prologue: A0 stored, A1 in regs, B0/B1 in flight ----
    lda(0);
    ldb(0, 0);
    ldb(1, 1);
    sta(0);
    lda(1);

    // ---- multistage main loop: ONE barrier per chunk ----
    #pragma unroll
    for (int c = 0; c < NC; c++) {
        if (c + 1 < NC) CP_WAIT1(); else CP_WAIT0();   // B(c) arrived (this thread)
        __syncthreads();                                // all threads past wait; stage c-? free
        if (c + 1 < NC) sta((c + 1) & 1);               // store A(c+1) (other stage)
        if (c + 2 < NC) {
            lda(c + 2);                                 // LDG A(c+2) into regs
            ldb(c + 2, (c + 2) % 3);                    // cp.async B(c+2) (free ring slot)
        }
        compute(c);
    }

    // ---- epilogue: bias (+fmap), direct global stores ----
    __syncthreads();
    const float* bias_s = (const float*)smem;
    const int r4 = lane >> 2;
    const int c2 = (lane & 3) * 2;
    #pragma unroll
    for (int mt = 0; mt < 2; mt++) {
        #pragma unroll
        for (int nt = 0; nt < 8; nt++) {
            const int col = wn * 64 + nt * 8 + c2;
            const float b0 = bias_s[col], b1 = bias_s[col + 1];
            const int row0 = m0 + wm * 32 + mt * 16 + r4;
            float2 o0, o1;
            o0.x = acc[mt][nt][0] + b0;  o0.y = acc[mt][nt][1] + b1;
            o1.x = acc[mt][nt][2] + b0;  o1.y = acc[mt][nt][3] + b1;
            if (MODE != 1) {
                o0.x = fmap(o0.x); o0.y = fmap(o0.y);
                o1.x = fmap(o1.x); o1.y = fmap(o1.y);
            }
            *(float2*)(outp + (size_t)row0 * 128 + col)       = o0;
            *(float2*)(outp + (size_t)(row0 + 8) * 128 + col) = o1;
        }
    }
}

// ---------------------------------------------------------------------------
// Attention reduction: 256 threads/block. Pass 1 split over two s-ranges
// (partials in smem, reduced once). Pass 2 split over two l-ranges with
// per-group named barriers. Thread t: group g=t>>7, tl=t&127, (h,dv) from tl.
// ---------------------------------------------------------------------------
__device__ __forceinline__ u64 pack2(float lo, float hi) {
    u64 r; asm("mov.b64 %0, {%1, %2};" : "=l"(r) : "f"(lo), "f"(hi)); return r;
}
__device__ __forceinline__ u64 fma2(u64 a, u64 b, u64 c) {
    u64 d; asm("fma.rn.f32x2 %0, %1, %2, %3;" : "=l"(d) : "l"(a), "l"(b), "l"(c)); return d;
}
__device__ __forceinline__ float2 unpack2(u64 v) {
    float2 f; asm("mov.b64 {%0, %1}, %2;" : "=f"(f.x), "=f"(f.y) : "l"(v)); return f;
}

__global__ __launch_bounds__(256)
void attn_kernel(float* __restrict__ out)
{
    __shared__ float KVp[2][HID * 16];   // per-group KV partials
    __shared__ float Ksp[2][HID];
    __shared__ float Qs[2][10][HID];
    __shared__ float accs[256];

    const int n  = blockIdx.x;
    const int t  = threadIdx.x;
    const int g  = t >> 7;          // s/l split group
    const int tl = t & 127;
    const int h  = tl >> 4;
    const int dv = tl & 15;

    const float* Kp = g_K + (size_t)n * (S_LEN * HID);
    const float* Vp = g_V + (size_t)n * (S_LEN * HID) + h * 16;

    const int s0 = g ? 38 : 0;
    const int s1 = g ? S_LEN : 38;

    u64 kv2[8];
    #pragma unroll
    for (int j = 0; j < 8; j++) kv2[j] = 0ULL;
    float ksum = 0.0f;

    #pragma unroll 4
    for (int s = s0; s < s1; s++) {
        const float kd = Kp[s * HID + tl];
        const float* vrow = Vp + s * HID;
        const ulonglong2 p0 = *(const ulonglong2*)(vrow);
        const ulonglong2 p1 = *(const ulonglong2*)(vrow + 4);
        const ulonglong2 p2 = *(const ulonglong2*)(vrow + 8);
        const ulonglong2 p3 = *(const ulonglong2*)(vrow + 12);
        ksum += kd;
        const u64 kd2 = pack2(kd, kd);
        kv2[0] = fma2(kd2, p0.x, kv2[0]);
        kv2[1] = fma2(kd2, p0.y, kv2[1]);
        kv2[2] = fma2(kd2, p1.x, kv2[2]);
        kv2[3] = fma2(kd2, p1.y, kv2[3]);
        kv2[4] = fma2(kd2, p2.x, kv2[4]);
        kv2[5] = fma2(kd2, p2.y, kv2[5]);
        kv2[6] = fma2(kd2, p3.x, kv2[6]);
        kv2[7] = fma2(kd2, p3.y, kv2[7]);
    }
    Ksp[g][tl] = ksum;
    #pragma unroll
    for (int j = 0; j < 8; j++) {
        float2 p = unpack2(kv2[j]);
        KVp[g][tl * 16 + 2 * j]     = p.x;
        KVp[g][tl * 16 + 2 * j + 1] = p.y;
    }
    __syncthreads();

    // reduce the two partials
    #pragma unroll
    for (int i = t; i < HID * 16; i += 256)
        KVp[0][i] += KVp[1][i];
    if (t < HID) Ksp[0][t] += Ksp[1][t];
    __syncthreads();

    // hoist loop-invariants into registers
    const int hb = h * 16;
    float ks_r[16], kvc[16];
    #pragma unroll
    for (int d = 0; d < 16; d++) {
        ks_r[d] = Ksp[0][hb + d];
        kvc[d]  = KVp[0][(hb + d) * 16 + dv];
    }

    // pass 2: group g handles l in [g*40, g*40+40), 4 chunks of 10
    float acc = 0.0f;
    const float* Qbase = g_Q + (size_t)n * (NQ * HID) + (size_t)g * 40 * HID;
    const int barid = g + 1;

    #pragma unroll
    for (int c = 0; c < 4; c++) {
        #pragma unroll
        for (int i = 0; i < 10; i++)
            Qs[g][i][tl] = Qbase[(c * 10 + i) * HID + tl];
        BAR_SYNC(barid, 128);
        #pragma unroll
        for (int i = 0; i < 10; i++) {
            float zs = EPS, tmp = 0.0f;
            #pragma unroll
            for (int d = 0; d < 16; d++) {
                const float qd = Qs[g][i][hb + d];
                zs  += qd * ks_r[d];
                tmp += qd * kvc[d];
            }
            acc += __fdividef(tmp, zs);
        }
        BAR_SYNC(barid, 128);
    }

    accs[t] = acc;
    __syncthreads();
    if (t < HID)
        out[(size_t)n * HID + t] = (accs[t] + accs[t + 128]) * (1.0f / NQ);
}

// ---------------------------------------------------------------------------
extern "C" void kernel_launch(void* const* d_in, const int* in_sizes, int n_in,
                              void* d_out, int out_size)
{
    const float* query = (const float*)d_in[0];
    const float* x     = (const float*)d_in[1];
    const float* guid  = (const float*)d_in[2];
    const float* Wq    = (const float*)d_in[3];
    const float* bq    = (const float*)d_in[4];
    const float* Wk    = (const float*)d_in[5];
    const float* bk    = (const float*)d_in[6];
    const float* Wv    = (const float*)d_in[7];
    const float* bv    = (const float*)d_in[8];
    float* out = (float*)d_out;

    static bool attr_done = false;
    if (!attr_done) {
        cudaFuncSetAttribute(gemm_mma<256,0>, cudaFuncAttributeMaxDynamicSharedMemorySize, SMEM_SZ);
        cudaFuncSetAttribute(gemm_mma<128,1>, cudaFuncAttributeMaxDynamicSharedMemorySize, SMEM_SZ);
        cudaFuncSetAttribute(gemm_mma<256,2>, cudaFuncAttributeMaxDynamicSharedMemorySize, SMEM_SZ);
        attr_done = true;
    }

    // Weight prep (destinations selected in device code)
    prep_w<0><<<128, 256>>>(Wk);
    prep_w<1><<<64, 256>>>(Wv);
    prep_w<2><<<128, 256>>>(Wq);

    // Multistage projections
    gemm_mma<256, 0><<<1386, 256, SMEM_SZ>>>(x, guid, bk);
    gemm_mma<128, 1><<<1386, 256, SMEM_SZ>>>(x, nullptr, bv);
    gemm_mma<256, 2><<<1440, 256, SMEM_SZ>>>(query, nullptr, bq);

    // Attention reduction -> out
    attn_kernel<<<NI, 256>>>(out);
}